// round 9
// baseline (speedup 1.0000x reference)
#include <cuda_runtime.h>

// RC timing on 200k independent 16-pin trees — mode-per-thread, block-level
// geometry dedup, nibble-packed parent indices for low register pressure.
//
// Block = 192 threads = 6 warps = 2 net-groups x 3 modes; warp (grp,mode)
// handles 32 nets, lane = net. fa_local[i] in [0,i) => bottom-up subtree
// sums exact in one descending sweep, top-down path sums in one ascending
// sweep. Dynamic parent indexing via lane-transposed shared scratch
// ([slot][lane] => bank == lane, conflict-free, thread-private columns).
//
// Parent indices are 4-bit (fa_local < 15), packed 8-per-uint32 => the whole
// parent table is 2 registers (pk0, pk1); unpacking is cheap ALU hidden under
// LDS latency. This plus fusing nc into pin_cap cuts regs ~80 -> ~66 so 5
// blocks fit per SM (30 warps) to hide the serial LDS chains.
//
// Output: out[(metric*3 + mode)*nPins + pin].

#define NS       16
#define TPB      192
#define NETS_PB  64

// byte offset into a [slot][lane] region for parent of slot i (compile-time i)
#define FB(i) (((((i) < 8 ? (pk0 >> ((i) * 4)) : (pk1 >> (((i) - 8) * 4))) & 15)) << 7)
#define WAT(fb) (*(float*)((char*)W + (fb)))

#define LD16(dst, src)                                                        \
    {                                                                         \
        const float4* _v = (const float4*)(src);                              \
        float4 _a = _v[0], _b = _v[1], _c = _v[2], _d = _v[3];                \
        dst[0]=_a.x; dst[1]=_a.y; dst[2]=_a.z; dst[3]=_a.w;                   \
        dst[4]=_b.x; dst[5]=_b.y; dst[6]=_b.z; dst[7]=_b.w;                   \
        dst[8]=_c.x; dst[9]=_c.y; dst[10]=_c.z; dst[11]=_c.w;                 \
        dst[12]=_d.x; dst[13]=_d.y; dst[14]=_d.z; dst[15]=_d.w;               \
    }

#define ST16(metric, arr)                                                     \
    {                                                                         \
        float* _po = out + (size_t)((metric) * 3 + mode) * nPins + g;         \
        _Pragma("unroll")                                                     \
        for (int _q = 0; _q < 4; _q++)                                        \
            ((float4*)_po)[_q] = make_float4(arr[4*_q], arr[4*_q+1],          \
                                             arr[4*_q+2], arr[4*_q+3]);       \
    }

__global__ void __launch_bounds__(TPB, 5)
rct_kernel(const float* __restrict__ x, const float* __restrict__ y,
           const int* __restrict__ fa,
           const float* __restrict__ c0, const float* __restrict__ c1,
           const float* __restrict__ c2,
           float* __restrict__ out, int nNets, int nPins)
{
    __shared__ float Wsm[6 * 512];       // per-warp sweep scratch, 12 KB
    __shared__ float RNsm[2 * 1024];     // per-group staging (x,y)/(res,nc), 8 KB
    __shared__ int2  Fsm[2 * 32];        // per-group packed parent nibbles

    const int wib  = threadIdx.x >> 5;   // 0..5
    const int lane = threadIdx.x & 31;
    const int mode = wib % 3;
    const int grp  = wib / 3;            // 0..1
    const int t    = blockIdx.x * NETS_PB + grp * 32 + lane;   // net id
    const bool act = (t < nNets);
    const int g    = t * NS;

    float* W  = Wsm  + wib * 512 + lane;        // [slot][lane] column
    float* RN = RNsm + grp * 1024 + lane * 2;   // float2 column
    int2*  F2 = Fsm  + grp * 32 + lane;

    unsigned pk0 = 0, pk1 = 0;           // 16 parent nibbles
    float res[NS];

    // ---- geometry (mode-0 warps only): res, nc, packed fa once per net ----
    if (act && mode == 0) {
        {
            const int4* fv = (const int4*)(fa + g);
            int4 a = fv[0], b = fv[1], c = fv[2], d = fv[3];
            int fl[NS] = { a.x, a.y, a.z, a.w, b.x, b.y, b.z, b.w,
                           c.x, c.y, c.z, c.w, d.x, d.y, d.z, d.w };
#pragma unroll
            for (int i = 0; i < 8; i++)  pk0 |= (unsigned)(fl[i] - g)     << (i * 4);
#pragma unroll
            for (int i = 8; i < NS; i++) pk1 |= (unsigned)(fl[i] - g)     << ((i - 8) * 4);
            *F2 = make_int2((int)pk0, (int)pk1);
        }
        float xr[NS], yr[NS];
        LD16(xr, x + g);
        LD16(yr, y + g);
#pragma unroll
        for (int i = 0; i < NS; i++)
            *(float2*)(RN + i * 64) = make_float2(xr[i], yr[i]);
        res[0] = 0.0f;
#pragma unroll
        for (int i = 1; i < NS; i++) {
            float2 p = *(const float2*)((char*)RN + (FB(i) << 1));
            res[i] = (fabsf(xr[i] - p.x) + fabsf(yr[i] - p.y)) * 5.0e-5f;
        }
        // wire caps: scatter half-edge caps up one level (own W region)
        W[0] = 0.0f;
#pragma unroll
        for (int i = 1; i < NS; i++) W[i * 32] = res[i];
#pragma unroll
        for (int i = NS - 1; i >= 1; i--) WAT(FB(i)) += res[i];
        // publish (res, nc) — overwrites xy staging (all reads done)
#pragma unroll
        for (int i = 0; i < NS; i++)
            *(float2*)(RN + i * 64) = make_float2(res[i], W[i * 32]);
    }

    __syncthreads();
    if (!act) return;

    if (mode != 0) {
        int2 pk = *F2;
        pk0 = (unsigned)pk.x; pk1 = (unsigned)pk.y;
    }

    const float* cb = (mode == 0) ? c0 : ((mode == 1) ? c1 : c2);

    // ---- pin caps (metric 0): pc = base_cap + nc (nc consumed in place) ----
    float u[NS], v[NS];          // u: pc -> ldelay -> beta ; v: load -> delay
    {
        float cr[NS];
        LD16(cr, cb + g);
#pragma unroll
        for (int i = 0; i < NS; i++) {
            float2 rn = *(const float2*)(RN + i * 64);
            res[i] = rn.x;
            u[i]   = cr[i] + rn.y;
        }
    }
    ST16(0, u);

    // ---- load: bottom-up subtree sum of pin_cap ---------------------------
#pragma unroll
    for (int i = 0; i < NS - 1; i++) W[i * 32] = u[i];   // slot 15 stays in reg
    v[NS - 1] = u[NS - 1];
    WAT(FB(NS - 1)) += v[NS - 1];
#pragma unroll
    for (int i = NS - 2; i >= 1; i--) {
        v[i] = W[i * 32];                                // descendants done
        WAT(FB(i)) += v[i];
    }
    v[0] = W[0];
    ST16(1, v);

    // ---- delay: top-down path sum; v: load -> delay -----------------------
    W[0] = 0.0f;
    v[0] = 0.0f;
#pragma unroll
    for (int i = 1; i < NS; i++) {
        float pd = WAT(FB(i));                           // parent = delay
        float d  = fmaf(res[i], v[i], pd);
        if (i < NS - 1) W[i * 32] = d;                   // 15 never a parent
        v[i] = d;
    }
    ST16(2, v);

    // ---- ldelay: bottom-up subtree sum of pc*delay; u: pc -> ldelay -------
#pragma unroll
    for (int i = 0; i < NS - 1; i++) W[i * 32] = u[i] * v[i];
    u[NS - 1] = u[NS - 1] * v[NS - 1];
    WAT(FB(NS - 1)) += u[NS - 1];
#pragma unroll
    for (int i = NS - 2; i >= 1; i--) {
        u[i] = W[i * 32];
        WAT(FB(i)) += u[i];
    }
    u[0] = W[0];
    ST16(3, u);

    // ---- beta: top-down path sum; u: ldelay -> beta -----------------------
    W[0] = 0.0f;
    u[0] = 0.0f;
#pragma unroll
    for (int i = 1; i < NS; i++) {
        float pb = WAT(FB(i));
        float b  = fmaf(res[i], u[i], pb);
        if (i < NS - 1) W[i * 32] = b;
        u[i] = b;
    }
    ST16(4, u);

    // ---- impulse = sqrt(max(2*beta - delay^2, 1e-12)) ---------------------
    {
        float* po = out + (size_t)(5 * 3 + mode) * nPins + g;
#pragma unroll
        for (int q = 0; q < 4; q++) {
            float o[4];
#pragma unroll
            for (int k = 0; k < 4; k++) {
                int i = 4 * q + k;
                if (i == 0) { o[k] = 1.0e-6f; continue; }
                float q2 = fmaf(-v[i], v[i], u[i] + u[i]);
                q2 = fmaxf(q2, 1.0e-12f);
                o[k] = q2 * rsqrtf(q2);                  // sqrt via MUFU.RSQ
            }
            ((float4*)po)[q] = make_float4(o[0], o[1], o[2], o[3]);
        }
    }
}

extern "C" void kernel_launch(void* const* d_in, const int* in_sizes, int n_in,
                              void* d_out, int out_size)
{
    const float* x  = (const float*)d_in[0];
    const float* y  = (const float*)d_in[1];
    const int*   fa = (const int*)  d_in[4];
    const float* c0 = (const float*)d_in[8];
    const float* c1 = (const float*)d_in[9];
    const float* c2 = (const float*)d_in[10];

    const int nPins = in_sizes[0];
    const int nNets = in_sizes[3] - 1;   // net_flat_topo_sort_start has nNets+1

    const int grid = (nNets + NETS_PB - 1) / NETS_PB;
    rct_kernel<<<grid, TPB>>>(x, y, fa, c0, c1, c2, (float*)d_out, nNets, nPins);
}

// round 10
// speedup vs baseline: 1.1266x; 1.1266x over previous
#include <cuda_runtime.h>

// RC timing on 200k independent 16-pin trees — mode-per-thread, block-level
// geometry dedup (R7 structure), with off-critical-path packing micro-cuts.
//
// Block = 192 threads = 6 warps = 2 net-groups x 3 modes; warp (grp,mode)
// handles 32 nets, lane = net. fa_local[i] in [0,i) => bottom-up subtree
// sums exact in one descending sweep, top-down path sums in one ascending
// sweep. Dynamic parent indexing via lane-transposed shared scratch
// ([slot][lane] => bank == lane, conflict-free, thread-private columns).
//
// vs R7: parent indices cross the warp boundary as 2 packed uint32
// (STS.64/LDS.64) and are unpacked ONCE into foff[16] registers — sweep
// address chains identical to R7 (R9 showed in-chain unpacking regresses).
// Mode-0 warps keep res/nc in registers across the barrier (no RN re-read).
// Output stores use streaming (.cs) hints.
//
// Output: out[(metric*3 + mode)*nPins + pin].

#define NS       16
#define TPB      192
#define NETS_PB  64

#define LD16(dst, src)                                                        \
    {                                                                         \
        const float4* _v = (const float4*)(src);                              \
        float4 _a = _v[0], _b = _v[1], _c = _v[2], _d = _v[3];                \
        dst[0]=_a.x; dst[1]=_a.y; dst[2]=_a.z; dst[3]=_a.w;                   \
        dst[4]=_b.x; dst[5]=_b.y; dst[6]=_b.z; dst[7]=_b.w;                   \
        dst[8]=_c.x; dst[9]=_c.y; dst[10]=_c.z; dst[11]=_c.w;                 \
        dst[12]=_d.x; dst[13]=_d.y; dst[14]=_d.z; dst[15]=_d.w;               \
    }

#define ST16(metric, arr)                                                     \
    {                                                                         \
        float* _po = out + (size_t)((metric) * 3 + mode) * nPins + g;         \
        _Pragma("unroll")                                                     \
        for (int _q = 0; _q < 4; _q++)                                        \
            __stcs((float4*)_po + _q,                                         \
                   make_float4(arr[4*_q], arr[4*_q+1],                        \
                               arr[4*_q+2], arr[4*_q+3]));                    \
    }

__global__ void __launch_bounds__(TPB, 4)
rct_kernel(const float* __restrict__ x, const float* __restrict__ y,
           const int* __restrict__ fa,
           const float* __restrict__ c0, const float* __restrict__ c1,
           const float* __restrict__ c2,
           float* __restrict__ out, int nNets, int nPins)
{
    __shared__ float Wsm[6 * 512];       // per-warp sweep scratch, 12 KB
    __shared__ float RNsm[2 * 1024];     // per-group (x,y)->(res,nc) fl2, 8 KB
    __shared__ int2  Fsm[2 * 32];        // per-group packed parent nibbles

    const int wib  = threadIdx.x >> 5;   // 0..5
    const int lane = threadIdx.x & 31;
    const int mode = wib % 3;
    const int grp  = wib / 3;            // 0..1
    const int t    = blockIdx.x * NETS_PB + grp * 32 + lane;   // net id
    const bool act = (t < nNets);
    const int g    = t * NS;

    float* W  = Wsm  + wib * 512 + lane;        // [slot][lane] column
    float* RN = RNsm + grp * 1024 + lane * 2;   // float2 column
    int2*  F2 = Fsm  + grp * 32 + lane;

    int   foff[NS];                      // parent slot * 32 (element offset)
    float res[NS];
    float ncr[NS];

    // ---- geometry (mode-0 warps only): res, nc, parents once per net ------
    if (act && mode == 0) {
        {
            const int4* fv = (const int4*)(fa + g);
            int4 a = fv[0], b = fv[1], c = fv[2], d = fv[3];
            int fl[NS] = { a.x, a.y, a.z, a.w, b.x, b.y, b.z, b.w,
                           c.x, c.y, c.z, c.w, d.x, d.y, d.z, d.w };
            unsigned pk0 = 0, pk1 = 0;
#pragma unroll
            for (int i = 0; i < 8; i++)  pk0 |= (unsigned)(fl[i] - g) << (i * 4);
#pragma unroll
            for (int i = 8; i < NS; i++) pk1 |= (unsigned)(fl[i] - g) << ((i - 8) * 4);
            *F2 = make_int2((int)pk0, (int)pk1);
#pragma unroll
            for (int i = 0; i < NS; i++) foff[i] = (fl[i] - g) * 32;
        }
        float xr[NS], yr[NS];
        LD16(xr, x + g);
        LD16(yr, y + g);
#pragma unroll
        for (int i = 0; i < NS; i++)
            *(float2*)(RN + i * 64) = make_float2(xr[i], yr[i]);
        res[0] = 0.0f;
#pragma unroll
        for (int i = 1; i < NS; i++) {
            float2 p = *(const float2*)(RN + foff[i] * 2);
            res[i] = (fabsf(xr[i] - p.x) + fabsf(yr[i] - p.y)) * 5.0e-5f;
        }
        // wire caps: scatter half-edge caps up one level (own W region)
        W[0] = 0.0f;
#pragma unroll
        for (int i = 1; i < NS; i++) W[i * 32] = res[i];
#pragma unroll
        for (int i = NS - 1; i >= 1; i--) W[foff[i]] += res[i];
        // capture nc in regs while publishing (res, nc) for modes 1/2
#pragma unroll
        for (int i = 0; i < NS; i++) {
            ncr[i] = W[i * 32];
            *(float2*)(RN + i * 64) = make_float2(res[i], ncr[i]);
        }
    }

    __syncthreads();
    if (!act) return;

    if (mode != 0) {
        int2 pk = *F2;
        unsigned pk0 = (unsigned)pk.x, pk1 = (unsigned)pk.y;
#pragma unroll
        for (int i = 0; i < 8; i++)  foff[i] = (int)((pk0 >> (i * 4)) & 15u) * 32;
#pragma unroll
        for (int i = 8; i < NS; i++) foff[i] = (int)((pk1 >> ((i - 8) * 4)) & 15u) * 32;
#pragma unroll
        for (int i = 0; i < NS; i++) {
            float2 rn = *(const float2*)(RN + i * 64);
            res[i] = rn.x; ncr[i] = rn.y;
        }
    }

    const float* cb = (mode == 0) ? c0 : ((mode == 1) ? c1 : c2);

    // ---- pin caps (metric 0) ----------------------------------------------
    float u[NS], v[NS];          // u: pc -> ldelay -> beta ; v: load -> delay
    {
        float cr[NS];
        LD16(cr, cb + g);
#pragma unroll
        for (int i = 0; i < NS; i++) u[i] = cr[i] + ncr[i];
    }
    ST16(0, u);

    // ---- load: bottom-up subtree sum of pin_cap ---------------------------
#pragma unroll
    for (int i = 0; i < NS - 1; i++) W[i * 32] = u[i];   // slot 15 stays in reg
    v[NS - 1] = u[NS - 1];
    W[foff[NS - 1]] += v[NS - 1];
#pragma unroll
    for (int i = NS - 2; i >= 1; i--) {
        v[i] = W[i * 32];                                // descendants done
        W[foff[i]] += v[i];
    }
    v[0] = W[0];
    ST16(1, v);

    // ---- delay: top-down path sum; v: load -> delay -----------------------
    W[0] = 0.0f;
    v[0] = 0.0f;                                         // root delay = 0
#pragma unroll
    for (int i = 1; i < NS; i++) {
        float pd = W[foff[i]];                           // parent = delay
        float d  = fmaf(res[i], v[i], pd);
        if (i < NS - 1) W[i * 32] = d;                   // 15 never a parent
        v[i] = d;
    }
    ST16(2, v);

    // ---- ldelay: bottom-up subtree sum of pc*delay; u: pc -> ldelay -------
#pragma unroll
    for (int i = 0; i < NS - 1; i++) W[i * 32] = u[i] * v[i];
    u[NS - 1] = u[NS - 1] * v[NS - 1];
    W[foff[NS - 1]] += u[NS - 1];
#pragma unroll
    for (int i = NS - 2; i >= 1; i--) {
        u[i] = W[i * 32];
        W[foff[i]] += u[i];
    }
    u[0] = W[0];
    ST16(3, u);

    // ---- beta: top-down path sum; u: ldelay -> beta -----------------------
    W[0] = 0.0f;
    u[0] = 0.0f;                                         // root beta = 0
#pragma unroll
    for (int i = 1; i < NS; i++) {
        float pb = W[foff[i]];
        float b  = fmaf(res[i], u[i], pb);
        if (i < NS - 1) W[i * 32] = b;
        u[i] = b;
    }
    ST16(4, u);

    // ---- impulse = sqrt(max(2*beta - delay^2, 1e-12)) ---------------------
    {
        float* po = out + (size_t)(5 * 3 + mode) * nPins + g;
#pragma unroll
        for (int q = 0; q < 4; q++) {
            float o[4];
#pragma unroll
            for (int k = 0; k < 4; k++) {
                int i = 4 * q + k;
                if (i == 0) { o[k] = 1.0e-6f; continue; }
                float q2 = fmaf(-v[i], v[i], u[i] + u[i]);
                q2 = fmaxf(q2, 1.0e-12f);
                o[k] = q2 * rsqrtf(q2);                  // sqrt via MUFU.RSQ
            }
            __stcs((float4*)po + q, make_float4(o[0], o[1], o[2], o[3]));
        }
    }
}

extern "C" void kernel_launch(void* const* d_in, const int* in_sizes, int n_in,
                              void* d_out, int out_size)
{
    const float* x  = (const float*)d_in[0];
    const float* y  = (const float*)d_in[1];
    const int*   fa = (const int*)  d_in[4];
    const float* c0 = (const float*)d_in[8];
    const float* c1 = (const float*)d_in[9];
    const float* c2 = (const float*)d_in[10];

    const int nPins = in_sizes[0];
    const int nNets = in_sizes[3] - 1;   // net_flat_topo_sort_start has nNets+1

    const int grid = (nNets + NETS_PB - 1) / NETS_PB;
    rct_kernel<<<grid, TPB>>>(x, y, fa, c0, c1, c2, (float*)d_out, nNets, nPins);
}

// round 11
// speedup vs baseline: 1.2181x; 1.0812x over previous
#include <cuda_runtime.h>

// RC timing on 200k independent 16-pin trees — mode-per-thread, block-level
// geometry dedup, and ALL global I/O warp-coalesced via swizzled shared
// staging.
//
// Key fix this round: thread-per-net makes natural global accesses 64B-stride
// per lane (16 cache lines per warp instruction -> ~16 L1 wavefronts). Every
// 2KB warp tile now goes through a per-warp staging buffer with swizzle
//   P(n,k) = 4n + ((k + n + (n>>1)) & 3)
// (conflict-free for both thread-major and lane-major float4 phases), so
// global ops are 4 coalesced 512B transactions (4 wavefronts each).
//
// Block = 192 threads = 6 warps = 2 net-groups x 3 modes; lane = net.
// fa_local[i] in [0,i) => single-sweep bottom-up / top-down recurrences via
// lane-transposed shared scratch [slot][lane] (bank == lane, no conflicts).
// Mode-0 warps compute geometry (res, wire caps, parents) once per net and
// publish through shared; modes 1/2 consume after one __syncthreads.
//
// Output: out[(metric*3 + mode)*nPins + pin].

#define NS       16
#define TPB      192
#define NETS_PB  64

__device__ __forceinline__ int swz(int n, int k) {
    return 4 * n + ((k + n + (n >> 1)) & 3);
}

// Warp-coalesced load of 16 floats/thread (thread n = lane owns chunk 4n..4n+3).
__device__ __forceinline__ void ld16w(float4* St, const float4* wb, int lane,
                                      bool full, bool act, float* dst)
{
    if (full) {
        float4 t0 = __ldg(wb + lane),      t1 = __ldg(wb + 32 + lane),
               t2 = __ldg(wb + 64 + lane), t3 = __ldg(wb + 96 + lane);
        St[swz(lane >> 2, lane & 3)] = t0;
        { int c = 32 + lane; St[swz(c >> 2, c & 3)] = t1; }
        { int c = 64 + lane; St[swz(c >> 2, c & 3)] = t2; }
        { int c = 96 + lane; St[swz(c >> 2, c & 3)] = t3; }
        __syncwarp();
#pragma unroll
        for (int k = 0; k < 4; k++) {
            float4 v = St[swz(lane, k)];
            dst[4*k] = v.x; dst[4*k+1] = v.y; dst[4*k+2] = v.z; dst[4*k+3] = v.w;
        }
    } else if (act) {
#pragma unroll
        for (int k = 0; k < 4; k++) {
            float4 v = __ldg(wb + 4 * lane + k);
            dst[4*k] = v.x; dst[4*k+1] = v.y; dst[4*k+2] = v.z; dst[4*k+3] = v.w;
        }
    } else {
#pragma unroll
        for (int i = 0; i < NS; i++) dst[i] = 0.0f;
    }
}

// Warp-coalesced store of 16 floats/thread.
__device__ __forceinline__ void st16w(float4* St, float4* wb, int lane,
                                      bool full, bool act, const float* a)
{
    if (full) {
#pragma unroll
        for (int k = 0; k < 4; k++)
            St[swz(lane, k)] = make_float4(a[4*k], a[4*k+1], a[4*k+2], a[4*k+3]);
        __syncwarp();
#pragma unroll
        for (int j = 0; j < 4; j++) {
            int c = j * 32 + lane;
            __stcs(wb + c, St[swz(c >> 2, c & 3)]);
        }
    } else if (act) {
#pragma unroll
        for (int k = 0; k < 4; k++)
            __stcs(wb + 4 * lane + k,
                   make_float4(a[4*k], a[4*k+1], a[4*k+2], a[4*k+3]));
    }
}

__global__ void __launch_bounds__(TPB, 4)
rct_kernel(const float* __restrict__ x, const float* __restrict__ y,
           const int* __restrict__ fa,
           const float* __restrict__ c0, const float* __restrict__ c1,
           const float* __restrict__ c2,
           float* __restrict__ out, int nNets, int nPins)
{
    __shared__ float4 Stg[6 * 2 * 128];  // per-warp ping-pong staging, 24 KB
    __shared__ float  Wsm[6 * 512];      // per-warp sweep scratch, 12 KB
    __shared__ float  RNsm[2 * 1024];    // per-group (x,y)->(res,nc) fl2, 8 KB
    __shared__ int2   Fsm[2 * 32];       // per-group packed parent nibbles

    const int wib  = threadIdx.x >> 5;   // 0..5
    const int lane = threadIdx.x & 31;
    const int mode = wib % 3;
    const int grp  = wib / 3;            // 0..1
    const int netbase = blockIdx.x * NETS_PB + grp * 32;
    const int t    = netbase + lane;     // net id
    const bool act = (t < nNets);
    const bool full = (netbase + 32 <= nNets);  // warp-uniform
    const int g    = t * NS;

    float4* S0 = Stg + wib * 256;               // two 128-float4 buffers
    float*  W  = Wsm  + wib * 512 + lane;       // [slot][lane] column
    float*  RN = RNsm + grp * 1024 + lane * 2;  // float2 column
    int2*   F2 = Fsm  + grp * 32 + lane;

    int   foff[NS];                      // parent slot * 32 (element offset)
    float res[NS];
    float ncr[NS];
    int   ph = 0;                        // staging ping-pong phase

    // ---- geometry (mode-0 warps): res, nc, parents once per net -----------
    if (mode == 0) {
        {
            float flf[NS];
            ld16w(S0 + (ph++ & 1) * 128, (const float4*)fa + (size_t)netbase * 4,
                  lane, full, act, flf);
            unsigned pk0 = 0, pk1 = 0;
#pragma unroll
            for (int i = 0; i < NS; i++) {
                int s = act ? (__float_as_int(flf[i]) - g) : 0;
                foff[i] = s * 32;
                if (i < 8) pk0 |= (unsigned)s << (i * 4);
                else       pk1 |= (unsigned)s << ((i - 8) * 4);
            }
            *F2 = make_int2((int)pk0, (int)pk1);
        }
        float xr[NS], yr[NS];
        ld16w(S0 + (ph++ & 1) * 128, (const float4*)x + (size_t)netbase * 4,
              lane, full, act, xr);
        ld16w(S0 + (ph++ & 1) * 128, (const float4*)y + (size_t)netbase * 4,
              lane, full, act, yr);
#pragma unroll
        for (int i = 0; i < NS; i++)
            *(float2*)(RN + i * 64) = make_float2(xr[i], yr[i]);
        res[0] = 0.0f;
#pragma unroll
        for (int i = 1; i < NS; i++) {
            float2 p = *(const float2*)(RN + foff[i] * 2);
            res[i] = (fabsf(xr[i] - p.x) + fabsf(yr[i] - p.y)) * 5.0e-5f;
        }
        // wire caps: scatter half-edge caps up one level (own W region)
        W[0] = 0.0f;
#pragma unroll
        for (int i = 1; i < NS; i++) W[i * 32] = res[i];
#pragma unroll
        for (int i = NS - 1; i >= 1; i--) W[foff[i]] += res[i];
        // capture nc in regs while publishing (res, nc) for modes 1/2
#pragma unroll
        for (int i = 0; i < NS; i++) {
            ncr[i] = W[i * 32];
            *(float2*)(RN + i * 64) = make_float2(res[i], ncr[i]);
        }
    }

    __syncthreads();

    if (mode != 0) {
        int2 pk = *F2;
        unsigned pk0 = (unsigned)pk.x, pk1 = (unsigned)pk.y;
#pragma unroll
        for (int i = 0; i < 8; i++)  foff[i] = (int)((pk0 >> (i * 4)) & 15u) * 32;
#pragma unroll
        for (int i = 8; i < NS; i++) foff[i] = (int)((pk1 >> ((i - 8) * 4)) & 15u) * 32;
#pragma unroll
        for (int i = 0; i < NS; i++) {
            float2 rn = *(const float2*)(RN + i * 64);
            res[i] = rn.x; ncr[i] = rn.y;
        }
    }

    const float* cb = (mode == 0) ? c0 : ((mode == 1) ? c1 : c2);
#define OB(metric) ((float4*)out + (size_t)((metric) * 3 + mode) * (nPins >> 2) \
                    + (size_t)netbase * 4)

    // ---- pin caps (metric 0) ----------------------------------------------
    float u[NS], v[NS];          // u: pc -> ldelay -> beta ; v: load -> delay
    {
        float cr[NS];
        ld16w(S0 + (ph++ & 1) * 128, (const float4*)cb + (size_t)netbase * 4,
              lane, full, act, cr);
#pragma unroll
        for (int i = 0; i < NS; i++) u[i] = cr[i] + ncr[i];
    }
    st16w(S0 + (ph++ & 1) * 128, OB(0), lane, full, act, u);

    // ---- load: bottom-up subtree sum of pin_cap ---------------------------
#pragma unroll
    for (int i = 0; i < NS - 1; i++) W[i * 32] = u[i];   // slot 15 stays in reg
    v[NS - 1] = u[NS - 1];
    W[foff[NS - 1]] += v[NS - 1];
#pragma unroll
    for (int i = NS - 2; i >= 1; i--) {
        v[i] = W[i * 32];                                // descendants done
        W[foff[i]] += v[i];
    }
    v[0] = W[0];
    st16w(S0 + (ph++ & 1) * 128, OB(1), lane, full, act, v);

    // ---- delay: top-down path sum; v: load -> delay -----------------------
    W[0] = 0.0f;
    v[0] = 0.0f;                                         // root delay = 0
#pragma unroll
    for (int i = 1; i < NS; i++) {
        float pd = W[foff[i]];                           // parent = delay
        float d  = fmaf(res[i], v[i], pd);
        if (i < NS - 1) W[i * 32] = d;                   // 15 never a parent
        v[i] = d;
    }
    st16w(S0 + (ph++ & 1) * 128, OB(2), lane, full, act, v);

    // ---- ldelay: bottom-up subtree sum of pc*delay; u: pc -> ldelay -------
#pragma unroll
    for (int i = 0; i < NS - 1; i++) W[i * 32] = u[i] * v[i];
    u[NS - 1] = u[NS - 1] * v[NS - 1];
    W[foff[NS - 1]] += u[NS - 1];
#pragma unroll
    for (int i = NS - 2; i >= 1; i--) {
        u[i] = W[i * 32];
        W[foff[i]] += u[i];
    }
    u[0] = W[0];
    st16w(S0 + (ph++ & 1) * 128, OB(3), lane, full, act, u);

    // ---- beta: top-down path sum; u: ldelay -> beta -----------------------
    W[0] = 0.0f;
    u[0] = 0.0f;                                         // root beta = 0
#pragma unroll
    for (int i = 1; i < NS; i++) {
        float pb = W[foff[i]];
        float b  = fmaf(res[i], u[i], pb);
        if (i < NS - 1) W[i * 32] = b;
        u[i] = b;
    }
    st16w(S0 + (ph++ & 1) * 128, OB(4), lane, full, act, u);

    // ---- impulse = sqrt(max(2*beta - delay^2, 1e-12)) ---------------------
    {
        float im[NS];
        im[0] = 1.0e-6f;
#pragma unroll
        for (int i = 1; i < NS; i++) {
            float q2 = fmaf(-v[i], v[i], u[i] + u[i]);
            q2 = fmaxf(q2, 1.0e-12f);
            im[i] = q2 * rsqrtf(q2);                     // sqrt via MUFU.RSQ
        }
        st16w(S0 + (ph++ & 1) * 128, OB(5), lane, full, act, im);
    }
#undef OB
}

extern "C" void kernel_launch(void* const* d_in, const int* in_sizes, int n_in,
                              void* d_out, int out_size)
{
    const float* x  = (const float*)d_in[0];
    const float* y  = (const float*)d_in[1];
    const int*   fa = (const int*)  d_in[4];
    const float* c0 = (const float*)d_in[8];
    const float* c1 = (const float*)d_in[9];
    const float* c2 = (const float*)d_in[10];

    const int nPins = in_sizes[0];
    const int nNets = in_sizes[3] - 1;   // net_flat_topo_sort_start has nNets+1

    const int grid = (nNets + NETS_PB - 1) / NETS_PB;
    rct_kernel<<<grid, TPB>>>(x, y, fa, c0, c1, c2, (float*)d_out, nNets, nPins);
}